// round 9
// baseline (speedup 1.0000x reference)
#include <cuda.h>
#include <cuda_runtime.h>
#include <cstdint>
#include <dlfcn.h>

#define B_  4
#define C_  256
#define H_  96
#define W_  128
#define P_  9
#define HW_ (H_ * W_)
#define CHW_ (C_ * H_ * W_)

#define TX  32           // x pixels per block
#define TY  4            // y pixels per block
#define PT  4            // x pixels per thread
#define THREADS 288      // (TX/PT) * 9 * TY
#define CC  8            // channels per stage
#define NSTAGE (C_ / CC) // 32
#define NBUF 3           // triple buffer, prefetch distance 2
#define HALO_W  40       // halo row width (floats); 160B rows
#define HALO_H  12

#define S2F_PER (CC * HALO_H * HALO_W)   // 3840 floats / buffer
#define S1F_PER (CC * TY * TX)           // 1024 floats / buffer
#define S2B_PER (S2F_PER * 4)            // 15360 B
#define S1B_PER (S1F_PER * 4)            // 4096 B
#define TX_BYTES ((uint32_t)(S1B_PER + S2B_PER))  // 19456 per stage (OOB fill counts)

typedef unsigned long long u64;

// ---- mbarrier primitives ----
__device__ __forceinline__ void mbar_init(uint32_t mbar, uint32_t cnt) {
    asm volatile("mbarrier.init.shared.b64 [%0], %1;" :: "r"(mbar), "r"(cnt) : "memory");
}
__device__ __forceinline__ void mbar_expect_tx(uint32_t mbar, uint32_t tx) {
    asm volatile("mbarrier.arrive.expect_tx.shared.b64 _, [%0], %1;"
                 :: "r"(mbar), "r"(tx) : "memory");
}
__device__ __forceinline__ void mbar_arrive(uint32_t mbar) {
    asm volatile("mbarrier.arrive.release.cta.shared::cta.b64 _, [%0];"
                 :: "r"(mbar) : "memory");
}
__device__ __forceinline__ void mbar_wait(uint32_t mbar, uint32_t parity) {
    uint32_t done;
    asm volatile(
        "{\n\t"
        ".reg .pred p;\n\t"
        "mbarrier.try_wait.parity.acquire.cta.shared::cta.b64 p, [%1], %2;\n\t"
        "selp.b32 %0, 1, 0, p;\n\t"
        "}"
        : "=r"(done) : "r"(mbar), "r"(parity) : "memory");
    if (!done) {
        asm volatile(
            "{\n\t"
            ".reg .pred P1;\n\t"
            "WAIT_LOOP_%=:\n\t"
            "mbarrier.try_wait.parity.acquire.cta.shared::cta.b64 P1, [%0], %1, 0x989680;\n\t"
            "@P1 bra.uni WAIT_DONE_%=;\n\t"
            "bra.uni WAIT_LOOP_%=;\n\t"
            "WAIT_DONE_%=:\n\t"
            "}"
            :: "r"(mbar), "r"(parity) : "memory");
    }
}
__device__ __forceinline__ void tma4d(uint32_t dst, const CUtensorMap* m,
                                      int x, int y, int z, int w, uint32_t mbar) {
    asm volatile(
        "cp.async.bulk.tensor.4d.shared::cta.global.tile.mbarrier::complete_tx::bytes "
        "[%0], [%1, {%2, %3, %4, %5}], [%6];"
        :: "r"(dst), "l"(m), "r"(x), "r"(y), "r"(z), "r"(w), "r"(mbar) : "memory");
}
__device__ __forceinline__ void fence_async_shared() {
    asm volatile("fence.proxy.async.shared::cta;" ::: "memory");
}

// ---- packed fp32 math ----
__device__ __forceinline__ u64 pk2(float lo, float hi) {
    u64 r;
    asm("mov.b64 %0, {%1, %2};" : "=l"(r) : "f"(lo), "f"(hi));
    return r;
}
__device__ __forceinline__ void fma2(u64& d, u64 a, u64 b) {
    asm("fma.rn.f32x2 %0, %1, %2, %0;" : "+l"(d) : "l"(a), "l"(b));
}
__device__ __forceinline__ void unpk2(float& lo, float& hi, u64 v) {
    asm("mov.b64 {%0, %1}, %2;" : "=f"(lo), "=f"(hi) : "l"(v));
}

__global__ void __launch_bounds__(THREADS, 3)
corr_kernel(const __grid_constant__ CUtensorMap tm1,
            const __grid_constant__ CUtensorMap tm2,
            float* __restrict__ out)
{
    __shared__ __align__(128) float s2[NBUF][S2F_PER];  // in2 halo tiles
    __shared__ __align__(128) float s1[NBUF][S1F_PER];  // in1 tiles
    __shared__ __align__(8)   u64   fullb[NBUF];
    __shared__ __align__(8)   u64   emptyb[NBUF];

    const int tid = threadIdx.x;
    const int b   = blockIdx.z;
    const int y0  = blockIdx.y * TY;
    const int x0  = blockIdx.x * TX;

    const uint32_t s2base = (uint32_t)__cvta_generic_to_shared(&s2[0][0]);
    const uint32_t s1base = (uint32_t)__cvta_generic_to_shared(&s1[0][0]);
    const uint32_t fbase  = (uint32_t)__cvta_generic_to_shared(&fullb[0]);
    const uint32_t ebase  = (uint32_t)__cvta_generic_to_shared(&emptyb[0]);

    // ---- compute roles: tid = (yy*9 + dy)*8 + g ----
    const int g   = tid & 7;
    const int dy  = (tid >> 3) % 9;
    const int yy  = tid / 72;

    u64 acc2[PT / 2][P_];
    #pragma unroll
    for (int t = 0; t < PT / 2; t++)
        #pragma unroll
        for (int d = 0; d < P_; d++)
            acc2[t][d] = 0ull;

    const int w_off = (yy + dy) * HALO_W + 4 * g;   // within s2 buffer (floats)
    const int a_off = yy * TX + 4 * g;              // within s1 buffer (floats)

    // ---- init barriers ----
    if (tid == 0) {
        #pragma unroll
        for (int i = 0; i < NBUF; i++) {
            mbar_init(fbase + 8u * i, 1);
            mbar_init(ebase + 8u * i, THREADS);
        }
        fence_async_shared();
    }
    __syncthreads();   // only block-wide barrier in the kernel

    // ---- prologue: fill stages 0 and 1 (tid 0 only) ----
    if (tid == 0) {
        #pragma unroll
        for (int ps = 0; ps < 2; ps++) {
            uint32_t mb = fbase + 8u * ps;
            mbar_expect_tx(mb, TX_BYTES);
            tma4d(s1base + ps * S1B_PER, &tm1, x0,     y0,     ps * CC, b, mb);
            tma4d(s2base + ps * S2B_PER, &tm2, x0 - 4, y0 - 4, ps * CC, b, mb);
        }
    }

    #pragma unroll 1
    for (int st = 0; st < NSTAGE; st++) {
        // producer: refill buffer (st+2)%3 once its readers (stage st-1) drained
        if (tid == 0 && st + 2 < NSTAGE) {
            const int s  = st + 2;
            const int pb = s % NBUF;
            if (st >= 1)   // first fill of each buffer needs no empty wait
                mbar_wait(ebase + 8u * pb, (uint32_t)((s / NBUF - 1) & 1));
            fence_async_shared();
            uint32_t mb = fbase + 8u * pb;
            mbar_expect_tx(mb, TX_BYTES);
            tma4d(s1base + pb * S1B_PER, &tm1, x0,     y0,     s * CC, b, mb);
            tma4d(s2base + pb * S2B_PER, &tm2, x0 - 4, y0 - 4, s * CC, b, mb);
        }

        // consumer: wait for stage st data
        const int cb = st % NBUF;
        mbar_wait(fbase + 8u * cb, (uint32_t)((st / NBUF) & 1));

        const float* wp = &s2[cb][w_off];
        const float* ap = &s1[cb][a_off];

        #pragma unroll 2
        for (int cc = 0; cc < CC; cc++) {
            const float4* wp4 = reinterpret_cast<const float4*>(wp);
            float4 w0 = wp4[0], w1 = wp4[1], w2 = wp4[2];
            float4 a  = *reinterpret_cast<const float4*>(ap);

            u64 av0 = pk2(a.x, a.y);
            u64 av1 = pk2(a.z, a.w);

            float wf[12];
            wf[0] = w0.x; wf[1]  = w0.y; wf[2]  = w0.z; wf[3]  = w0.w;
            wf[4] = w1.x; wf[5]  = w1.y; wf[6]  = w1.z; wf[7]  = w1.w;
            wf[8] = w2.x; wf[9]  = w2.y; wf[10] = w2.z; wf[11] = w2.w;

            u64 wq[11];
            #pragma unroll
            for (int k = 0; k < 11; k++)
                wq[k] = pk2(wf[k], wf[k + 1]);

            #pragma unroll
            for (int d = 0; d < P_; d++) {
                fma2(acc2[0][d], av0, wq[d]);
                fma2(acc2[1][d], av1, wq[d + 2]);
            }

            wp += HALO_H * HALO_W;
            ap += TY * TX;
        }

        // release: this thread is done reading buffer cb
        mbar_arrive(ebase + 8u * cb);
    }

    // ---- write output: out[b][dy][d][y0+yy][x0+4g .. +3] ----
    {
        const size_t hw = (size_t)HW_;
        float* obase = out + (((size_t)b * P_ + dy) * P_) * hw
                     + (size_t)(y0 + yy) * W_ + x0 + 4 * g;
        #pragma unroll
        for (int d = 0; d < P_; d++) {
            float4 v;
            unpk2(v.x, v.y, acc2[0][d]);
            unpk2(v.z, v.w, acc2[1][d]);
            *reinterpret_cast<float4*>(obase + (size_t)d * hw) = v;
        }
    }
}

// ---- host: resolve cuTensorMapEncodeTiled robustly (no -lcuda needed) ----
typedef CUresult (*EncodeTiledFn)(
    CUtensorMap*, CUtensorMapDataType, cuuint32_t, void*,
    const cuuint64_t*, const cuuint64_t*, const cuuint32_t*, const cuuint32_t*,
    CUtensorMapInterleave, CUtensorMapSwizzle, CUtensorMapL2promotion,
    CUtensorMapFloatOOBfill);

static EncodeTiledFn resolve_encode_fn() {
    void* fn = nullptr;
#if CUDART_VERSION >= 12050
    cudaDriverEntryPointQueryResult qres = cudaDriverEntryPointSuccess;
    if (cudaGetDriverEntryPointByVersion("cuTensorMapEncodeTiled", &fn, 12000,
                                         cudaEnableDefault, &qres) == cudaSuccess
        && qres == cudaDriverEntryPointSuccess && fn)
        return (EncodeTiledFn)fn;
    fn = nullptr;
#endif
    void* h = dlopen("libcuda.so.1", RTLD_LAZY | RTLD_GLOBAL);
    if (!h) h = dlopen("libcuda.so", RTLD_LAZY | RTLD_GLOBAL);
    if (h) fn = dlsym(h, "cuTensorMapEncodeTiled");
    if (!fn) fn = dlsym(RTLD_DEFAULT, "cuTensorMapEncodeTiled");
    return (EncodeTiledFn)fn;
}

extern "C" void kernel_launch(void* const* d_in, const int* in_sizes, int n_in,
                              void* d_out, int out_size) {
    void* in1 = d_in[0];
    void* in2 = d_in[1];
    float* out = (float*)d_out;

    EncodeTiledFn enc = resolve_encode_fn();
    if (!enc) return;

    cuuint64_t dims[4]    = {W_, H_, C_, B_};
    cuuint64_t strides[3] = {(cuuint64_t)W_ * 4,
                             (cuuint64_t)HW_ * 4,
                             (cuuint64_t)CHW_ * 4};
    cuuint32_t estr[4]    = {1, 1, 1, 1};

    CUtensorMap tm1, tm2;
    cuuint32_t box1[4] = {TX, TY, CC, 1};            // in1 tile
    enc(&tm1, CU_TENSOR_MAP_DATA_TYPE_FLOAT32, 4, in1, dims, strides, box1, estr,
        CU_TENSOR_MAP_INTERLEAVE_NONE, CU_TENSOR_MAP_SWIZZLE_NONE,
        CU_TENSOR_MAP_L2_PROMOTION_L2_128B, CU_TENSOR_MAP_FLOAT_OOB_FILL_NONE);

    cuuint32_t box2[4] = {HALO_W, HALO_H, CC, 1};    // in2 halo (OOB zero-filled)
    enc(&tm2, CU_TENSOR_MAP_DATA_TYPE_FLOAT32, 4, in2, dims, strides, box2, estr,
        CU_TENSOR_MAP_INTERLEAVE_NONE, CU_TENSOR_MAP_SWIZZLE_NONE,
        CU_TENSOR_MAP_L2_PROMOTION_L2_128B, CU_TENSOR_MAP_FLOAT_OOB_FILL_NONE);

    dim3 grid(W_ / TX, H_ / TY, B_);   // (4, 24, 4) = 384 blocks
    dim3 block(THREADS);               // 288
    corr_kernel<<<grid, block>>>(tm1, tm2, out);
}

// round 10
// speedup vs baseline: 1.1067x; 1.1067x over previous
#include <cuda.h>
#include <cuda_runtime.h>
#include <cstdint>
#include <dlfcn.h>

#define B_  4
#define C_  256
#define H_  96
#define W_  128
#define P_  9
#define HW_ (H_ * W_)
#define HW4_ (HW_ / 4)
#define CHW_ (C_ * H_ * W_)

#define TX  32           // x pixels per block
#define TY  4            // y pixels per block
#define PT  4            // x pixels per thread
#define THREADS 288      // (TX/PT) * 9 * TY
#define CC  8            // channels per stage
#define NSTAGE (C_ / CC) // 32
#define NBUF 4           // quad buffer; barrier every 2 stages
#define HALO_W  40       // halo row width (floats); 160B rows
#define HALO_H  12

#define S2F_PER (CC * HALO_H * HALO_W)   // 3840 floats / buffer
#define S2B_PER (S2F_PER * 4)            // 15360 B
#define TXB ((uint32_t)S2B_PER)          // expect_tx bytes (OOB fill counts)

typedef unsigned long long u64;

// ---- mbarrier primitives ----
__device__ __forceinline__ void mbar_init(uint32_t mbar, uint32_t cnt) {
    asm volatile("mbarrier.init.shared.b64 [%0], %1;" :: "r"(mbar), "r"(cnt) : "memory");
}
__device__ __forceinline__ void mbar_expect_tx(uint32_t mbar, uint32_t tx) {
    asm volatile("mbarrier.arrive.expect_tx.shared.b64 _, [%0], %1;"
                 :: "r"(mbar), "r"(tx) : "memory");
}
__device__ __forceinline__ void mbar_wait(uint32_t mbar, uint32_t parity) {
    uint32_t done;
    asm volatile(
        "{\n\t"
        ".reg .pred p;\n\t"
        "mbarrier.try_wait.parity.acquire.cta.shared::cta.b64 p, [%1], %2;\n\t"
        "selp.b32 %0, 1, 0, p;\n\t"
        "}"
        : "=r"(done) : "r"(mbar), "r"(parity) : "memory");
    if (!done) {
        asm volatile(
            "{\n\t"
            ".reg .pred P1;\n\t"
            "WAIT_LOOP_%=:\n\t"
            "mbarrier.try_wait.parity.acquire.cta.shared::cta.b64 P1, [%0], %1, 0x989680;\n\t"
            "@P1 bra.uni WAIT_DONE_%=;\n\t"
            "bra.uni WAIT_LOOP_%=;\n\t"
            "WAIT_DONE_%=:\n\t"
            "}"
            :: "r"(mbar), "r"(parity) : "memory");
    }
}
__device__ __forceinline__ void tma4d(uint32_t dst, const CUtensorMap* m,
                                      int x, int y, int z, int w, uint32_t mbar) {
    asm volatile(
        "cp.async.bulk.tensor.4d.shared::cta.global.tile.mbarrier::complete_tx::bytes "
        "[%0], [%1, {%2, %3, %4, %5}], [%6];"
        :: "r"(dst), "l"(m), "r"(x), "r"(y), "r"(z), "r"(w), "r"(mbar) : "memory");
}
__device__ __forceinline__ void fence_async_shared() {
    asm volatile("fence.proxy.async.shared::cta;" ::: "memory");
}

// ---- packed fp32 math ----
__device__ __forceinline__ u64 pk2(float lo, float hi) {
    u64 r;
    asm("mov.b64 %0, {%1, %2};" : "=l"(r) : "f"(lo), "f"(hi));
    return r;
}
__device__ __forceinline__ void fma2(u64& d, u64 a, u64 b) {
    asm("fma.rn.f32x2 %0, %1, %2, %0;" : "+l"(d) : "l"(a), "l"(b));
}
__device__ __forceinline__ void unpk2(float& lo, float& hi, u64 v) {
    asm("mov.b64 {%0, %1}, %2;" : "=f"(lo), "=f"(hi) : "l"(v));
}

__global__ void __launch_bounds__(THREADS, 3)
corr_kernel(const __grid_constant__ CUtensorMap tm2,
            const float* __restrict__ in1,
            float* __restrict__ out)
{
    __shared__ __align__(128) float s2[NBUF][S2F_PER];  // in2 halo tiles (61440 B)
    __shared__ __align__(8)   u64   mbar[NBUF];

    const int tid = threadIdx.x;
    const int b   = blockIdx.z;
    const int y0  = blockIdx.y * TY;
    const int x0  = blockIdx.x * TX;

    const uint32_t s2base = (uint32_t)__cvta_generic_to_shared(&s2[0][0]);
    const uint32_t mbase  = (uint32_t)__cvta_generic_to_shared(&mbar[0]);

    // ---- compute roles: tid = (yy*9 + dy)*8 + g ----
    const int g   = tid & 7;
    const int dy  = (tid >> 3) % 9;
    const int yy  = tid / 72;

    u64 acc2[PT / 2][P_];
    #pragma unroll
    for (int t = 0; t < PT / 2; t++)
        #pragma unroll
        for (int d = 0; d < P_; d++)
            acc2[t][d] = 0ull;

    const int w_off = (yy + dy) * HALO_W + 4 * g;   // within s2 buffer (floats)
    // in1: one float4 per channel, read via LDG with register prefetch
    const float4* ap4 = reinterpret_cast<const float4*>(in1 + (size_t)b * CHW_)
                      + ((y0 + yy) * W_ + x0 + 4 * g) / 4;

    // ---- init barriers ----
    if (tid == 0) {
        #pragma unroll
        for (int i = 0; i < NBUF; i++)
            mbar_init(mbase + 8u * i, 1);
        fence_async_shared();
    }
    __syncthreads();

    // ---- prologue: fill stages 0 and 1; prefetch in1 ch 0 and 1 ----
    if (tid == 0) {
        #pragma unroll
        for (int ps = 0; ps < 2; ps++) {
            uint32_t mb = mbase + 8u * ps;
            mbar_expect_tx(mb, TXB);
            tma4d(s2base + ps * S2B_PER, &tm2, x0 - 4, y0 - 4, ps * CC, b, mb);
        }
    }
    float4 a_cur = __ldg(ap4);
    float4 a_nxt = __ldg(ap4 + HW4_);

    #pragma unroll 1
    for (int st = 0; st < NSTAGE; st++) {
        if ((st & 1) == 0) {
            __syncthreads();   // all warps finished stage st-1
            if (tid == 0) {
                #pragma unroll
                for (int k = 2; k <= 3; k++) {
                    const int s = st + k;          // overwrites stage s-4 <= st-1: safe
                    if (s < NSTAGE) {
                        const int pb = s % NBUF;
                        uint32_t mb = mbase + 8u * pb;
                        mbar_expect_tx(mb, TXB);
                        tma4d(s2base + pb * S2B_PER, &tm2,
                              x0 - 4, y0 - 4, s * CC, b, mb);
                    }
                }
            }
        }

        // wait for stage st halo
        const int cb = st % NBUF;
        mbar_wait(mbase + 8u * cb, (uint32_t)((st / NBUF) & 1));

        const float* wp = &s2[cb][w_off];

        #pragma unroll 2
        for (int cc = 0; cc < CC; cc++) {
            // rotate in1 prefetch pipeline (distance 2)
            float4 a = a_cur;
            a_cur = a_nxt;
            const int pfch = (st * CC + cc + 2) & (C_ - 1);   // wrap keeps in-bounds
            a_nxt = __ldg(ap4 + (size_t)pfch * HW4_);

            const float4* wp4 = reinterpret_cast<const float4*>(wp);
            float4 w0 = wp4[0], w1 = wp4[1], w2 = wp4[2];

            u64 av0 = pk2(a.x, a.y);
            u64 av1 = pk2(a.z, a.w);

            float wf[12];
            wf[0] = w0.x; wf[1]  = w0.y; wf[2]  = w0.z; wf[3]  = w0.w;
            wf[4] = w1.x; wf[5]  = w1.y; wf[6]  = w1.z; wf[7]  = w1.w;
            wf[8] = w2.x; wf[9]  = w2.y; wf[10] = w2.z; wf[11] = w2.w;

            u64 wq[11];
            #pragma unroll
            for (int k = 0; k < 11; k++)
                wq[k] = pk2(wf[k], wf[k + 1]);

            #pragma unroll
            for (int d = 0; d < P_; d++) {
                fma2(acc2[0][d], av0, wq[d]);
                fma2(acc2[1][d], av1, wq[d + 2]);
            }

            wp += HALO_H * HALO_W;
        }
    }

    // ---- write output: out[b][dy][d][y0+yy][x0+4g .. +3] ----
    {
        const size_t hw = (size_t)HW_;
        float* obase = out + (((size_t)b * P_ + dy) * P_) * hw
                     + (size_t)(y0 + yy) * W_ + x0 + 4 * g;
        #pragma unroll
        for (int d = 0; d < P_; d++) {
            float4 v;
            unpk2(v.x, v.y, acc2[0][d]);
            unpk2(v.z, v.w, acc2[1][d]);
            *reinterpret_cast<float4*>(obase + (size_t)d * hw) = v;
        }
    }
}

// ---- host: resolve cuTensorMapEncodeTiled robustly (no -lcuda needed) ----
typedef CUresult (*EncodeTiledFn)(
    CUtensorMap*, CUtensorMapDataType, cuuint32_t, void*,
    const cuuint64_t*, const cuuint64_t*, const cuuint32_t*, const cuuint32_t*,
    CUtensorMapInterleave, CUtensorMapSwizzle, CUtensorMapL2promotion,
    CUtensorMapFloatOOBfill);

static EncodeTiledFn resolve_encode_fn() {
    void* fn = nullptr;
#if CUDART_VERSION >= 12050
    cudaDriverEntryPointQueryResult qres = cudaDriverEntryPointSuccess;
    if (cudaGetDriverEntryPointByVersion("cuTensorMapEncodeTiled", &fn, 12000,
                                         cudaEnableDefault, &qres) == cudaSuccess
        && qres == cudaDriverEntryPointSuccess && fn)
        return (EncodeTiledFn)fn;
    fn = nullptr;
#endif
    void* h = dlopen("libcuda.so.1", RTLD_LAZY | RTLD_GLOBAL);
    if (!h) h = dlopen("libcuda.so", RTLD_LAZY | RTLD_GLOBAL);
    if (h) fn = dlsym(h, "cuTensorMapEncodeTiled");
    if (!fn) fn = dlsym(RTLD_DEFAULT, "cuTensorMapEncodeTiled");
    return (EncodeTiledFn)fn;
}

extern "C" void kernel_launch(void* const* d_in, const int* in_sizes, int n_in,
                              void* d_out, int out_size) {
    void* in1 = d_in[0];
    void* in2 = d_in[1];
    float* out = (float*)d_out;

    EncodeTiledFn enc = resolve_encode_fn();
    if (!enc) return;

    cuuint64_t dims[4]    = {W_, H_, C_, B_};
    cuuint64_t strides[3] = {(cuuint64_t)W_ * 4,
                             (cuuint64_t)HW_ * 4,
                             (cuuint64_t)CHW_ * 4};
    cuuint32_t estr[4]    = {1, 1, 1, 1};

    CUtensorMap tm2;
    cuuint32_t box2[4] = {HALO_W, HALO_H, CC, 1};    // in2 halo (OOB zero-filled)
    enc(&tm2, CU_TENSOR_MAP_DATA_TYPE_FLOAT32, 4, in2, dims, strides, box2, estr,
        CU_TENSOR_MAP_INTERLEAVE_NONE, CU_TENSOR_MAP_SWIZZLE_NONE,
        CU_TENSOR_MAP_L2_PROMOTION_L2_128B, CU_TENSOR_MAP_FLOAT_OOB_FILL_NONE);

    dim3 grid(W_ / TX, H_ / TY, B_);   // (4, 24, 4) = 384 blocks
    dim3 block(THREADS);               // 288
    corr_kernel<<<grid, block>>>(tm2, (const float*)in1, out);
}

// round 11
// speedup vs baseline: 1.1296x; 1.0207x over previous
#include <cuda.h>
#include <cuda_runtime.h>
#include <cstdint>
#include <dlfcn.h>

#define B_  4
#define C_  256
#define H_  96
#define W_  128
#define P_  9
#define HW_ (H_ * W_)
#define CHW_ (C_ * H_ * W_)

#define TX  32           // x pixels per block
#define TY  4            // y pixels per block
#define PT  4            // x pixels per thread
#define THREADS 288      // (TX/PT) * 9 * TY
#define CC  8            // channels per stage
#define NSTAGE (C_ / CC) // 32
#define NBUF 3           // triple buffer, prefetch distance 3 (issue after drain)
#define HALO_W  40       // halo row width (floats); 160B rows
#define HALO_H  12

#define S2F_PER (CC * HALO_H * HALO_W)   // 3840 floats / buffer
#define S1F_PER (CC * TY * TX)           // 1024 floats / buffer
#define S2B_PER (S2F_PER * 4)            // 15360 B
#define S1B_PER (S1F_PER * 4)            // 4096 B
#define TX_BYTES ((uint32_t)(S1B_PER + S2B_PER))  // 19456 per stage (OOB fill counts)

typedef unsigned long long u64;

// ---- mbarrier / named-barrier primitives ----
__device__ __forceinline__ void mbar_init(uint32_t mbar, uint32_t cnt) {
    asm volatile("mbarrier.init.shared.b64 [%0], %1;" :: "r"(mbar), "r"(cnt) : "memory");
}
__device__ __forceinline__ void mbar_expect_tx(uint32_t mbar, uint32_t tx) {
    asm volatile("mbarrier.arrive.expect_tx.shared.b64 _, [%0], %1;"
                 :: "r"(mbar), "r"(tx) : "memory");
}
__device__ __forceinline__ void mbar_wait(uint32_t mbar, uint32_t parity) {
    uint32_t done;
    asm volatile(
        "{\n\t"
        ".reg .pred p;\n\t"
        "mbarrier.try_wait.parity.acquire.cta.shared::cta.b64 p, [%1], %2;\n\t"
        "selp.b32 %0, 1, 0, p;\n\t"
        "}"
        : "=r"(done) : "r"(mbar), "r"(parity) : "memory");
    if (!done) {
        asm volatile(
            "{\n\t"
            ".reg .pred P1;\n\t"
            "WAIT_LOOP_%=:\n\t"
            "mbarrier.try_wait.parity.acquire.cta.shared::cta.b64 P1, [%0], %1, 0x989680;\n\t"
            "@P1 bra.uni WAIT_DONE_%=;\n\t"
            "bra.uni WAIT_LOOP_%=;\n\t"
            "WAIT_DONE_%=:\n\t"
            "}"
            :: "r"(mbar), "r"(parity) : "memory");
    }
}
__device__ __forceinline__ void bar_arrive(uint32_t id, uint32_t cnt) {
    asm volatile("bar.arrive %0, %1;" :: "r"(id), "r"(cnt) : "memory");
}
__device__ __forceinline__ void bar_sync_named(uint32_t id, uint32_t cnt) {
    asm volatile("bar.sync %0, %1;" :: "r"(id), "r"(cnt) : "memory");
}
__device__ __forceinline__ void tma4d(uint32_t dst, const CUtensorMap* m,
                                      int x, int y, int z, int w, uint32_t mbar) {
    asm volatile(
        "cp.async.bulk.tensor.4d.shared::cta.global.tile.mbarrier::complete_tx::bytes "
        "[%0], [%1, {%2, %3, %4, %5}], [%6];"
        :: "r"(dst), "l"(m), "r"(x), "r"(y), "r"(z), "r"(w), "r"(mbar) : "memory");
}
__device__ __forceinline__ void fence_async_shared() {
    asm volatile("fence.proxy.async.shared::cta;" ::: "memory");
}

// ---- packed fp32 math ----
__device__ __forceinline__ u64 pk2(float lo, float hi) {
    u64 r;
    asm("mov.b64 %0, {%1, %2};" : "=l"(r) : "f"(lo), "f"(hi));
    return r;
}
__device__ __forceinline__ void fma2(u64& d, u64 a, u64 b) {
    asm("fma.rn.f32x2 %0, %1, %2, %0;" : "+l"(d) : "l"(a), "l"(b));
}
__device__ __forceinline__ void unpk2(float& lo, float& hi, u64 v) {
    asm("mov.b64 {%0, %1}, %2;" : "=f"(lo), "=f"(hi) : "l"(v));
}

__global__ void __launch_bounds__(THREADS, 3)
corr_kernel(const __grid_constant__ CUtensorMap tm1,
            const __grid_constant__ CUtensorMap tm2,
            float* __restrict__ out)
{
    __shared__ __align__(128) float s2[NBUF][S2F_PER];  // in2 halo tiles
    __shared__ __align__(128) float s1[NBUF][S1F_PER];  // in1 tiles
    __shared__ __align__(8)   u64   fullb[NBUF];

    const int tid = threadIdx.x;
    const int wid = tid >> 5;
    const int b   = blockIdx.z;
    const int y0  = blockIdx.y * TY;
    const int x0  = blockIdx.x * TX;

    const uint32_t s2base = (uint32_t)__cvta_generic_to_shared(&s2[0][0]);
    const uint32_t s1base = (uint32_t)__cvta_generic_to_shared(&s1[0][0]);
    const uint32_t fbase  = (uint32_t)__cvta_generic_to_shared(&fullb[0]);

    // ---- compute roles: tid = (yy*9 + dy)*8 + g ----
    const int g   = tid & 7;
    const int dy  = (tid >> 3) % 9;
    const int yy  = tid / 72;

    u64 acc2[PT / 2][P_];
    #pragma unroll
    for (int t = 0; t < PT / 2; t++)
        #pragma unroll
        for (int d = 0; d < P_; d++)
            acc2[t][d] = 0ull;

    const int w_off = (yy + dy) * HALO_W + 4 * g;   // within s2 buffer (floats)
    const int a_off = yy * TX + 4 * g;              // within s1 buffer (floats)

    // ---- init mbarriers ----
    if (tid == 0) {
        #pragma unroll
        for (int i = 0; i < NBUF; i++)
            mbar_init(fbase + 8u * i, 1);
        fence_async_shared();
    }
    __syncthreads();   // only block-wide barrier

    // ---- prologue: fill stages 0..2 (tid 0 only) ----
    if (tid == 0) {
        #pragma unroll
        for (int ps = 0; ps < NBUF; ps++) {
            uint32_t mb = fbase + 8u * ps;
            mbar_expect_tx(mb, TX_BYTES);
            tma4d(s1base + ps * S1B_PER, &tm1, x0,     y0,     ps * CC, b, mb);
            tma4d(s2base + ps * S2B_PER, &tm2, x0 - 4, y0 - 4, ps * CC, b, mb);
        }
    }

    #pragma unroll 1
    for (int st = 0; st < NSTAGE; st++) {
        const int cb = st % NBUF;

        // wait for stage st data (filled 3 stages ahead)
        mbar_wait(fbase + 8u * cb, (uint32_t)((st / NBUF) & 1));

        const float* wp = &s2[cb][w_off];
        const float* ap = &s1[cb][a_off];

        #pragma unroll 2
        for (int cc = 0; cc < CC; cc++) {
            const float4* wp4 = reinterpret_cast<const float4*>(wp);
            float4 w0 = wp4[0], w1 = wp4[1], w2 = wp4[2];
            float4 a  = *reinterpret_cast<const float4*>(ap);

            u64 av0 = pk2(a.x, a.y);
            u64 av1 = pk2(a.z, a.w);

            float wf[12];
            wf[0] = w0.x; wf[1]  = w0.y; wf[2]  = w0.z; wf[3]  = w0.w;
            wf[4] = w1.x; wf[5]  = w1.y; wf[6]  = w1.z; wf[7]  = w1.w;
            wf[8] = w2.x; wf[9]  = w2.y; wf[10] = w2.z; wf[11] = w2.w;

            u64 wq[11];
            #pragma unroll
            for (int k = 0; k < 11; k++)
                wq[k] = pk2(wf[k], wf[k + 1]);

            #pragma unroll
            for (int d = 0; d < P_; d++) {
                fma2(acc2[0][d], av0, wq[d]);
                fma2(acc2[1][d], av1, wq[d + 2]);
            }

            wp += HALO_H * HALO_W;
            ap += TY * TX;
        }

        // stage-drain protocol: consumers post non-blocking arrive;
        // leader warp absorbs the wait, then refills this buffer for st+3.
        if (st + NBUF < NSTAGE) {
            if (wid == 0) {
                bar_sync_named(1u + cb, THREADS);   // waits for 256 arrivals + own 32
                if (tid == 0) {
                    const int s = st + NBUF;        // same buffer cb
                    uint32_t mb = fbase + 8u * cb;
                    mbar_expect_tx(mb, TX_BYTES);
                    tma4d(s1base + cb * S1B_PER, &tm1, x0,     y0,     s * CC, b, mb);
                    tma4d(s2base + cb * S2B_PER, &tm2, x0 - 4, y0 - 4, s * CC, b, mb);
                }
            } else {
                bar_arrive(1u + cb, THREADS);       // non-blocking
            }
        }
    }

    // ---- write output: out[b][dy][d][y0+yy][x0+4g .. +3] ----
    {
        const size_t hw = (size_t)HW_;
        float* obase = out + (((size_t)b * P_ + dy) * P_) * hw
                     + (size_t)(y0 + yy) * W_ + x0 + 4 * g;
        #pragma unroll
        for (int d = 0; d < P_; d++) {
            float4 v;
            unpk2(v.x, v.y, acc2[0][d]);
            unpk2(v.z, v.w, acc2[1][d]);
            *reinterpret_cast<float4*>(obase + (size_t)d * hw) = v;
        }
    }
}

// ---- host: resolve cuTensorMapEncodeTiled robustly (no -lcuda needed) ----
typedef CUresult (*EncodeTiledFn)(
    CUtensorMap*, CUtensorMapDataType, cuuint32_t, void*,
    const cuuint64_t*, const cuuint64_t*, const cuuint32_t*, const cuuint32_t*,
    CUtensorMapInterleave, CUtensorMapSwizzle, CUtensorMapL2promotion,
    CUtensorMapFloatOOBfill);

static EncodeTiledFn resolve_encode_fn() {
    void* fn = nullptr;
#if CUDART_VERSION >= 12050
    cudaDriverEntryPointQueryResult qres = cudaDriverEntryPointSuccess;
    if (cudaGetDriverEntryPointByVersion("cuTensorMapEncodeTiled", &fn, 12000,
                                         cudaEnableDefault, &qres) == cudaSuccess
        && qres == cudaDriverEntryPointSuccess && fn)
        return (EncodeTiledFn)fn;
    fn = nullptr;
#endif
    void* h = dlopen("libcuda.so.1", RTLD_LAZY | RTLD_GLOBAL);
    if (!h) h = dlopen("libcuda.so", RTLD_LAZY | RTLD_GLOBAL);
    if (h) fn = dlsym(h, "cuTensorMapEncodeTiled");
    if (!fn) fn = dlsym(RTLD_DEFAULT, "cuTensorMapEncodeTiled");
    return (EncodeTiledFn)fn;
}

extern "C" void kernel_launch(void* const* d_in, const int* in_sizes, int n_in,
                              void* d_out, int out_size) {
    void* in1 = d_in[0];
    void* in2 = d_in[1];
    float* out = (float*)d_out;

    EncodeTiledFn enc = resolve_encode_fn();
    if (!enc) return;

    cuuint64_t dims[4]    = {W_, H_, C_, B_};
    cuuint64_t strides[3] = {(cuuint64_t)W_ * 4,
                             (cuuint64_t)HW_ * 4,
                             (cuuint64_t)CHW_ * 4};
    cuuint32_t estr[4]    = {1, 1, 1, 1};

    CUtensorMap tm1, tm2;
    cuuint32_t box1[4] = {TX, TY, CC, 1};            // in1 tile
    enc(&tm1, CU_TENSOR_MAP_DATA_TYPE_FLOAT32, 4, in1, dims, strides, box1, estr,
        CU_TENSOR_MAP_INTERLEAVE_NONE, CU_TENSOR_MAP_SWIZZLE_NONE,
        CU_TENSOR_MAP_L2_PROMOTION_L2_128B, CU_TENSOR_MAP_FLOAT_OOB_FILL_NONE);

    cuuint32_t box2[4] = {HALO_W, HALO_H, CC, 1};    // in2 halo (OOB zero-filled)
    enc(&tm2, CU_TENSOR_MAP_DATA_TYPE_FLOAT32, 4, in2, dims, strides, box2, estr,
        CU_TENSOR_MAP_INTERLEAVE_NONE, CU_TENSOR_MAP_SWIZZLE_NONE,
        CU_TENSOR_MAP_L2_PROMOTION_L2_128B, CU_TENSOR_MAP_FLOAT_OOB_FILL_NONE);

    dim3 grid(W_ / TX, H_ / TY, B_);   // (4, 24, 4) = 384 blocks
    dim3 block(THREADS);               // 288
    corr_kernel<<<grid, block>>>(tm1, tm2, out);
}

// round 12
// speedup vs baseline: 1.2887x; 1.1409x over previous
#include <cuda.h>
#include <cuda_runtime.h>
#include <cstdint>
#include <dlfcn.h>

#define B_  4
#define C_  256
#define H_  96
#define W_  128
#define P_  9
#define HW_ (H_ * W_)
#define CHW_ (C_ * H_ * W_)

#define TX  32           // x pixels per block
#define TY  6            // y pixels per block
#define PT  4            // x pixels per thread
#define ACTIVE 432       // 8g * 9dy * 6yy
#define THREADS 448      // padded to warp multiple (14 warps)
#define CC  8            // channels per stage
#define NSTAGE (C_ / CC) // 32
#define NBUF 3           // triple buffer, prefetch distance 2
#define HALO_W  40       // halo row width (floats); 160B rows
#define HALO_H  14       // TY + 8

#define S2F_PER (CC * HALO_H * HALO_W)   // 4480 floats / buffer
#define S1F_PER (CC * TY * TX)           // 1536 floats / buffer
#define S2B_PER (S2F_PER * 4)            // 17920 B
#define S1B_PER (S1F_PER * 4)            // 6144 B
#define TX_BYTES ((uint32_t)(S1B_PER + S2B_PER))  // 24064 per stage (OOB fill counts)

typedef unsigned long long u64;

// ---- mbarrier primitives (proven forms) ----
__device__ __forceinline__ void mbar_init(uint32_t mbar, uint32_t cnt) {
    asm volatile("mbarrier.init.shared.b64 [%0], %1;" :: "r"(mbar), "r"(cnt) : "memory");
}
__device__ __forceinline__ void mbar_expect_tx(uint32_t mbar, uint32_t tx) {
    asm volatile("mbarrier.arrive.expect_tx.shared.b64 _, [%0], %1;"
                 :: "r"(mbar), "r"(tx) : "memory");
}
__device__ __forceinline__ void mbar_wait(uint32_t mbar, uint32_t parity) {
    uint32_t done;
    asm volatile(
        "{\n\t"
        ".reg .pred p;\n\t"
        "mbarrier.try_wait.parity.acquire.cta.shared::cta.b64 p, [%1], %2;\n\t"
        "selp.b32 %0, 1, 0, p;\n\t"
        "}"
        : "=r"(done) : "r"(mbar), "r"(parity) : "memory");
    if (!done) {
        asm volatile(
            "{\n\t"
            ".reg .pred P1;\n\t"
            "WAIT_LOOP_%=:\n\t"
            "mbarrier.try_wait.parity.acquire.cta.shared::cta.b64 P1, [%0], %1, 0x989680;\n\t"
            "@P1 bra.uni WAIT_DONE_%=;\n\t"
            "bra.uni WAIT_LOOP_%=;\n\t"
            "WAIT_DONE_%=:\n\t"
            "}"
            :: "r"(mbar), "r"(parity) : "memory");
    }
}
__device__ __forceinline__ void tma4d(uint32_t dst, const CUtensorMap* m,
                                      int x, int y, int z, int w, uint32_t mbar) {
    asm volatile(
        "cp.async.bulk.tensor.4d.shared::cta.global.tile.mbarrier::complete_tx::bytes "
        "[%0], [%1, {%2, %3, %4, %5}], [%6];"
        :: "r"(dst), "l"(m), "r"(x), "r"(y), "r"(z), "r"(w), "r"(mbar) : "memory");
}
__device__ __forceinline__ void fence_async_shared() {
    asm volatile("fence.proxy.async.shared::cta;" ::: "memory");
}

// ---- packed fp32 math ----
__device__ __forceinline__ u64 pk2(float lo, float hi) {
    u64 r;
    asm("mov.b64 %0, {%1, %2};" : "=l"(r) : "f"(lo), "f"(hi));
    return r;
}
__device__ __forceinline__ void fma2(u64& d, u64 a, u64 b) {
    asm("fma.rn.f32x2 %0, %1, %2, %0;" : "+l"(d) : "l"(a), "l"(b));
}
__device__ __forceinline__ void unpk2(float& lo, float& hi, u64 v) {
    asm("mov.b64 {%0, %1}, %2;" : "=f"(lo), "=f"(hi) : "l"(v));
}

__global__ void __launch_bounds__(THREADS, 2)
corr_kernel(const __grid_constant__ CUtensorMap tm1,
            const __grid_constant__ CUtensorMap tm2,
            float* __restrict__ out)
{
    __shared__ __align__(128) float s2[NBUF][S2F_PER];  // in2 halo tiles
    __shared__ __align__(128) float s1[NBUF][S1F_PER];  // in1 tiles
    __shared__ __align__(8)   u64   fullb[NBUF];

    const int tid = threadIdx.x;
    const int b   = blockIdx.z;
    const int y0  = blockIdx.y * TY;
    const int x0  = blockIdx.x * TX;

    const uint32_t s2base = (uint32_t)__cvta_generic_to_shared(&s2[0][0]);
    const uint32_t s1base = (uint32_t)__cvta_generic_to_shared(&s1[0][0]);
    const uint32_t fbase  = (uint32_t)__cvta_generic_to_shared(&fullb[0]);

    // ---- compute roles: tid = (yy*9 + dy)*8 + g ; pads clamp yy (stores guarded) ----
    const bool active = (tid < ACTIVE);
    const int g   = tid & 7;
    const int dy  = (tid >> 3) % 9;
    const int yyr = tid / 72;
    const int yy  = active ? yyr : (TY - 1);

    u64 acc2[PT / 2][P_];
    #pragma unroll
    for (int t = 0; t < PT / 2; t++)
        #pragma unroll
        for (int d = 0; d < P_; d++)
            acc2[t][d] = 0ull;

    const int w_off = (yy + dy) * HALO_W + 4 * g;   // within s2 buffer (floats)
    const int a_off = yy * TX + 4 * g;              // within s1 buffer (floats)

    // ---- init mbarriers ----
    if (tid == 0) {
        #pragma unroll
        for (int i = 0; i < NBUF; i++)
            mbar_init(fbase + 8u * i, 1);
        fence_async_shared();
    }
    __syncthreads();

    // ---- prologue: issue stages 0 and 1 (tid 0 only) ----
    if (tid == 0) {
        #pragma unroll
        for (int ps = 0; ps < 2; ps++) {
            uint32_t mb = fbase + 8u * ps;
            mbar_expect_tx(mb, TX_BYTES);
            tma4d(s1base + ps * S1B_PER, &tm1, x0,     y0,     ps * CC, b, mb);
            tma4d(s2base + ps * S2B_PER, &tm2, x0 - 4, y0 - 4, ps * CC, b, mb);
        }
    }

    #pragma unroll 1
    for (int st = 0; st < NSTAGE; st++) {
        __syncthreads();   // all reads of buffer (st+2)%3 (done at stage st-1)
                           // complete before it is refilled below
        if (tid == 0 && st + 2 < NSTAGE) {
            const int pb = (st + 2) % NBUF;
            uint32_t mb = fbase + 8u * pb;
            mbar_expect_tx(mb, TX_BYTES);
            tma4d(s1base + pb * S1B_PER, &tm1, x0,     y0,     (st + 2) * CC, b, mb);
            tma4d(s2base + pb * S2B_PER, &tm2, x0 - 4, y0 - 4, (st + 2) * CC, b, mb);
        }

        // wait for stage st data
        mbar_wait(fbase + 8u * (st % NBUF), (uint32_t)((st / NBUF) & 1));

        const float* wp = &s2[st % NBUF][w_off];
        const float* ap = &s1[st % NBUF][a_off];

        #pragma unroll 2
        for (int cc = 0; cc < CC; cc++) {
            const float4* wp4 = reinterpret_cast<const float4*>(wp);
            float4 w0 = wp4[0], w1 = wp4[1], w2 = wp4[2];
            float4 a  = *reinterpret_cast<const float4*>(ap);

            u64 av0 = pk2(a.x, a.y);
            u64 av1 = pk2(a.z, a.w);

            float wf[12];
            wf[0] = w0.x; wf[1]  = w0.y; wf[2]  = w0.z; wf[3]  = w0.w;
            wf[4] = w1.x; wf[5]  = w1.y; wf[6]  = w1.z; wf[7]  = w1.w;
            wf[8] = w2.x; wf[9]  = w2.y; wf[10] = w2.z; wf[11] = w2.w;

            u64 wq[11];
            #pragma unroll
            for (int k = 0; k < 11; k++)
                wq[k] = pk2(wf[k], wf[k + 1]);

            #pragma unroll
            for (int d = 0; d < P_; d++) {
                fma2(acc2[0][d], av0, wq[d]);
                fma2(acc2[1][d], av1, wq[d + 2]);
            }

            wp += HALO_H * HALO_W;
            ap += TY * TX;
        }
    }

    // ---- write output: out[b][dy][d][y0+yy][x0+4g .. +3] ----
    if (active) {
        const size_t hw = (size_t)HW_;
        float* obase = out + (((size_t)b * P_ + dy) * P_) * hw
                     + (size_t)(y0 + yy) * W_ + x0 + 4 * g;
        #pragma unroll
        for (int d = 0; d < P_; d++) {
            float4 v;
            unpk2(v.x, v.y, acc2[0][d]);
            unpk2(v.z, v.w, acc2[1][d]);
            *reinterpret_cast<float4*>(obase + (size_t)d * hw) = v;
        }
    }
}

// ---- host: resolve cuTensorMapEncodeTiled robustly (no -lcuda needed) ----
typedef CUresult (*EncodeTiledFn)(
    CUtensorMap*, CUtensorMapDataType, cuuint32_t, void*,
    const cuuint64_t*, const cuuint64_t*, const cuuint32_t*, const cuuint32_t*,
    CUtensorMapInterleave, CUtensorMapSwizzle, CUtensorMapL2promotion,
    CUtensorMapFloatOOBfill);

static EncodeTiledFn resolve_encode_fn() {
    void* fn = nullptr;
#if CUDART_VERSION >= 12050
    cudaDriverEntryPointQueryResult qres = cudaDriverEntryPointSuccess;
    if (cudaGetDriverEntryPointByVersion("cuTensorMapEncodeTiled", &fn, 12000,
                                         cudaEnableDefault, &qres) == cudaSuccess
        && qres == cudaDriverEntryPointSuccess && fn)
        return (EncodeTiledFn)fn;
    fn = nullptr;
#endif
    void* h = dlopen("libcuda.so.1", RTLD_LAZY | RTLD_GLOBAL);
    if (!h) h = dlopen("libcuda.so", RTLD_LAZY | RTLD_GLOBAL);
    if (h) fn = dlsym(h, "cuTensorMapEncodeTiled");
    if (!fn) fn = dlsym(RTLD_DEFAULT, "cuTensorMapEncodeTiled");
    return (EncodeTiledFn)fn;
}

extern "C" void kernel_launch(void* const* d_in, const int* in_sizes, int n_in,
                              void* d_out, int out_size) {
    void* in1 = d_in[0];
    void* in2 = d_in[1];
    float* out = (float*)d_out;

    EncodeTiledFn enc = resolve_encode_fn();
    if (!enc) return;

    cuuint64_t dims[4]    = {W_, H_, C_, B_};
    cuuint64_t strides[3] = {(cuuint64_t)W_ * 4,
                             (cuuint64_t)HW_ * 4,
                             (cuuint64_t)CHW_ * 4};
    cuuint32_t estr[4]    = {1, 1, 1, 1};

    CUtensorMap tm1, tm2;
    cuuint32_t box1[4] = {TX, TY, CC, 1};            // in1 tile (128B rows)
    enc(&tm1, CU_TENSOR_MAP_DATA_TYPE_FLOAT32, 4, in1, dims, strides, box1, estr,
        CU_TENSOR_MAP_INTERLEAVE_NONE, CU_TENSOR_MAP_SWIZZLE_NONE,
        CU_TENSOR_MAP_L2_PROMOTION_L2_128B, CU_TENSOR_MAP_FLOAT_OOB_FILL_NONE);

    cuuint32_t box2[4] = {HALO_W, HALO_H, CC, 1};    // in2 halo (OOB zero-filled)
    enc(&tm2, CU_TENSOR_MAP_DATA_TYPE_FLOAT32, 4, in2, dims, strides, box2, estr,
        CU_TENSOR_MAP_INTERLEAVE_NONE, CU_TENSOR_MAP_SWIZZLE_NONE,
        CU_TENSOR_MAP_L2_PROMOTION_L2_128B, CU_TENSOR_MAP_FLOAT_OOB_FILL_NONE);

    dim3 grid(W_ / TX, H_ / TY, B_);   // (4, 16, 4) = 256 blocks
    dim3 block(THREADS);               // 448 (432 active)
    corr_kernel<<<grid, block>>>(tm1, tm2, out);
}

// round 13
// speedup vs baseline: 1.2937x; 1.0039x over previous
#include <cuda.h>
#include <cuda_runtime.h>
#include <cstdint>
#include <dlfcn.h>

#define B_  4
#define C_  256
#define H_  96
#define W_  128
#define P_  9
#define HW_ (H_ * W_)
#define CHW_ (C_ * H_ * W_)

#define TX  32           // x pixels per block
#define TY  6            // y pixels per block
#define PT  4            // x pixels per thread
#define ACTIVE 432       // 8g * 9dy * 6yy
#define THREADS 448      // padded to warp multiple (14 warps)
#define CC  16           // channels per stage
#define NSTAGE (C_ / CC) // 16
#define NBUF 2           // double buffer, prefetch distance 1
#define HALO_W  40       // halo row width (floats); 160B rows
#define HALO_H  14       // TY + 8

#define S2F_PER (CC * HALO_H * HALO_W)   // 8960 floats / buffer
#define S1F_PER (CC * TY * TX)           // 3072 floats / buffer
#define S2B_PER (S2F_PER * 4)            // 35840 B
#define S1B_PER (S1F_PER * 4)            // 12288 B
#define TX_BYTES ((uint32_t)(S1B_PER + S2B_PER))  // 48128 per stage (OOB fill counts)

typedef unsigned long long u64;

// ---- mbarrier primitives (proven forms) ----
__device__ __forceinline__ void mbar_init(uint32_t mbar, uint32_t cnt) {
    asm volatile("mbarrier.init.shared.b64 [%0], %1;" :: "r"(mbar), "r"(cnt) : "memory");
}
__device__ __forceinline__ void mbar_expect_tx(uint32_t mbar, uint32_t tx) {
    asm volatile("mbarrier.arrive.expect_tx.shared.b64 _, [%0], %1;"
                 :: "r"(mbar), "r"(tx) : "memory");
}
__device__ __forceinline__ void mbar_wait(uint32_t mbar, uint32_t parity) {
    uint32_t done;
    asm volatile(
        "{\n\t"
        ".reg .pred p;\n\t"
        "mbarrier.try_wait.parity.acquire.cta.shared::cta.b64 p, [%1], %2;\n\t"
        "selp.b32 %0, 1, 0, p;\n\t"
        "}"
        : "=r"(done) : "r"(mbar), "r"(parity) : "memory");
    if (!done) {
        asm volatile(
            "{\n\t"
            ".reg .pred P1;\n\t"
            "WAIT_LOOP_%=:\n\t"
            "mbarrier.try_wait.parity.acquire.cta.shared::cta.b64 P1, [%0], %1, 0x989680;\n\t"
            "@P1 bra.uni WAIT_DONE_%=;\n\t"
            "bra.uni WAIT_LOOP_%=;\n\t"
            "WAIT_DONE_%=:\n\t"
            "}"
            :: "r"(mbar), "r"(parity) : "memory");
    }
}
__device__ __forceinline__ void tma4d(uint32_t dst, const CUtensorMap* m,
                                      int x, int y, int z, int w, uint32_t mbar) {
    asm volatile(
        "cp.async.bulk.tensor.4d.shared::cta.global.tile.mbarrier::complete_tx::bytes "
        "[%0], [%1, {%2, %3, %4, %5}], [%6];"
        :: "r"(dst), "l"(m), "r"(x), "r"(y), "r"(z), "r"(w), "r"(mbar) : "memory");
}
__device__ __forceinline__ void fence_async_shared() {
    asm volatile("fence.proxy.async.shared::cta;" ::: "memory");
}

// ---- packed fp32 math ----
__device__ __forceinline__ u64 pk2(float lo, float hi) {
    u64 r;
    asm("mov.b64 %0, {%1, %2};" : "=l"(r) : "f"(lo), "f"(hi));
    return r;
}
__device__ __forceinline__ void fma2(u64& d, u64 a, u64 b) {
    asm("fma.rn.f32x2 %0, %1, %2, %0;" : "+l"(d) : "l"(a), "l"(b));
}
__device__ __forceinline__ void unpk2(float& lo, float& hi, u64 v) {
    asm("mov.b64 {%0, %1}, %2;" : "=f"(lo), "=f"(hi) : "l"(v));
}

__global__ void __launch_bounds__(THREADS, 2)
corr_kernel(const __grid_constant__ CUtensorMap tm1,
            const __grid_constant__ CUtensorMap tm2,
            float* __restrict__ out)
{
    __shared__ __align__(128) float s2[NBUF][S2F_PER];  // in2 halo tiles
    __shared__ __align__(128) float s1[NBUF][S1F_PER];  // in1 tiles
    __shared__ __align__(8)   u64   fullb[NBUF];

    const int tid = threadIdx.x;
    const int b   = blockIdx.z;
    const int y0  = blockIdx.y * TY;
    const int x0  = blockIdx.x * TX;

    const uint32_t s2base = (uint32_t)__cvta_generic_to_shared(&s2[0][0]);
    const uint32_t s1base = (uint32_t)__cvta_generic_to_shared(&s1[0][0]);
    const uint32_t fbase  = (uint32_t)__cvta_generic_to_shared(&fullb[0]);

    // ---- compute roles: tid = (yy*9 + dy)*8 + g ; pads clamp yy (stores guarded) ----
    const bool active = (tid < ACTIVE);
    const int g   = tid & 7;
    const int dy  = (tid >> 3) % 9;
    const int yyr = tid / 72;
    const int yy  = active ? yyr : (TY - 1);

    u64 acc2[PT / 2][P_];
    #pragma unroll
    for (int t = 0; t < PT / 2; t++)
        #pragma unroll
        for (int d = 0; d < P_; d++)
            acc2[t][d] = 0ull;

    const int w_off = (yy + dy) * HALO_W + 4 * g;   // within s2 buffer (floats)
    const int a_off = yy * TX + 4 * g;              // within s1 buffer (floats)

    // ---- init mbarriers ----
    if (tid == 0) {
        #pragma unroll
        for (int i = 0; i < NBUF; i++)
            mbar_init(fbase + 8u * i, 1);
        fence_async_shared();
    }
    __syncthreads();

    // ---- prologue: fill stage 0 -> buf0, stage 1 -> buf1 (tid 0 only) ----
    if (tid == 0) {
        #pragma unroll
        for (int ps = 0; ps < 2; ps++) {
            uint32_t mb = fbase + 8u * ps;
            mbar_expect_tx(mb, TX_BYTES);
            tma4d(s1base + ps * S1B_PER, &tm1, x0,     y0,     ps * CC, b, mb);
            tma4d(s2base + ps * S2B_PER, &tm2, x0 - 4, y0 - 4, ps * CC, b, mb);
        }
    }

    #pragma unroll 1
    for (int st = 0; st < NSTAGE; st++) {
        if (st >= 1) {
            __syncthreads();   // stage st-1 fully drained by all warps
            // refill the buffer stage st-1 occupied with stage st+1
            if (tid == 0 && st + 1 < NSTAGE) {
                const int pb = (st + 1) % NBUF;    // == (st-1) % NBUF
                uint32_t mb = fbase + 8u * pb;
                mbar_expect_tx(mb, TX_BYTES);
                tma4d(s1base + pb * S1B_PER, &tm1, x0,     y0,     (st + 1) * CC, b, mb);
                tma4d(s2base + pb * S2B_PER, &tm2, x0 - 4, y0 - 4, (st + 1) * CC, b, mb);
            }
        }

        // wait for stage st data (issued one stage ahead)
        mbar_wait(fbase + 8u * (st % NBUF), (uint32_t)((st / NBUF) & 1));

        const float* wp = &s2[st % NBUF][w_off];
        const float* ap = &s1[st % NBUF][a_off];

        #pragma unroll 2
        for (int cc = 0; cc < CC; cc++) {
            const float4* wp4 = reinterpret_cast<const float4*>(wp);
            float4 w0 = wp4[0], w1 = wp4[1], w2 = wp4[2];
            float4 a  = *reinterpret_cast<const float4*>(ap);

            u64 av0 = pk2(a.x, a.y);
            u64 av1 = pk2(a.z, a.w);

            float wf[12];
            wf[0] = w0.x; wf[1]  = w0.y; wf[2]  = w0.z; wf[3]  = w0.w;
            wf[4] = w1.x; wf[5]  = w1.y; wf[6]  = w1.z; wf[7]  = w1.w;
            wf[8] = w2.x; wf[9]  = w2.y; wf[10] = w2.z; wf[11] = w2.w;

            u64 wq[11];
            #pragma unroll
            for (int k = 0; k < 11; k++)
                wq[k] = pk2(wf[k], wf[k + 1]);

            #pragma unroll
            for (int d = 0; d < P_; d++) {
                fma2(acc2[0][d], av0, wq[d]);
                fma2(acc2[1][d], av1, wq[d + 2]);
            }

            wp += HALO_H * HALO_W;
            ap += TY * TX;
        }
    }

    // ---- write output: out[b][dy][d][y0+yy][x0+4g .. +3] ----
    if (active) {
        const size_t hw = (size_t)HW_;
        float* obase = out + (((size_t)b * P_ + dy) * P_) * hw
                     + (size_t)(y0 + yy) * W_ + x0 + 4 * g;
        #pragma unroll
        for (int d = 0; d < P_; d++) {
            float4 v;
            unpk2(v.x, v.y, acc2[0][d]);
            unpk2(v.z, v.w, acc2[1][d]);
            *reinterpret_cast<float4*>(obase + (size_t)d * hw) = v;
        }
    }
}

// ---- host: resolve cuTensorMapEncodeTiled robustly (no -lcuda needed) ----
typedef CUresult (*EncodeTiledFn)(
    CUtensorMap*, CUtensorMapDataType, cuuint32_t, void*,
    const cuuint64_t*, const cuuint64_t*, const cuuint32_t*, const cuuint32_t*,
    CUtensorMapInterleave, CUtensorMapSwizzle, CUtensorMapL2promotion,
    CUtensorMapFloatOOBfill);

static EncodeTiledFn resolve_encode_fn() {
    void* fn = nullptr;
#if CUDART_VERSION >= 12050
    cudaDriverEntryPointQueryResult qres = cudaDriverEntryPointSuccess;
    if (cudaGetDriverEntryPointByVersion("cuTensorMapEncodeTiled", &fn, 12000,
                                         cudaEnableDefault, &qres) == cudaSuccess
        && qres == cudaDriverEntryPointSuccess && fn)
        return (EncodeTiledFn)fn;
    fn = nullptr;
#endif
    void* h = dlopen("libcuda.so.1", RTLD_LAZY | RTLD_GLOBAL);
    if (!h) h = dlopen("libcuda.so", RTLD_LAZY | RTLD_GLOBAL);
    if (h) fn = dlsym(h, "cuTensorMapEncodeTiled");
    if (!fn) fn = dlsym(RTLD_DEFAULT, "cuTensorMapEncodeTiled");
    return (EncodeTiledFn)fn;
}

extern "C" void kernel_launch(void* const* d_in, const int* in_sizes, int n_in,
                              void* d_out, int out_size) {
    void* in1 = d_in[0];
    void* in2 = d_in[1];
    float* out = (float*)d_out;

    EncodeTiledFn enc = resolve_encode_fn();
    if (!enc) return;

    cuuint64_t dims[4]    = {W_, H_, C_, B_};
    cuuint64_t strides[3] = {(cuuint64_t)W_ * 4,
                             (cuuint64_t)HW_ * 4,
                             (cuuint64_t)CHW_ * 4};
    cuuint32_t estr[4]    = {1, 1, 1, 1};

    CUtensorMap tm1, tm2;
    cuuint32_t box1[4] = {TX, TY, CC, 1};            // in1 tile (128B rows)
    enc(&tm1, CU_TENSOR_MAP_DATA_TYPE_FLOAT32, 4, in1, dims, strides, box1, estr,
        CU_TENSOR_MAP_INTERLEAVE_NONE, CU_TENSOR_MAP_SWIZZLE_NONE,
        CU_TENSOR_MAP_L2_PROMOTION_L2_128B, CU_TENSOR_MAP_FLOAT_OOB_FILL_NONE);

    cuuint32_t box2[4] = {HALO_W, HALO_H, CC, 1};    // in2 halo (OOB zero-filled)
    enc(&tm2, CU_TENSOR_MAP_DATA_TYPE_FLOAT32, 4, in2, dims, strides, box2, estr,
        CU_TENSOR_MAP_INTERLEAVE_NONE, CU_TENSOR_MAP_SWIZZLE_NONE,
        CU_TENSOR_MAP_L2_PROMOTION_L2_128B, CU_TENSOR_MAP_FLOAT_OOB_FILL_NONE);

    dim3 grid(W_ / TX, H_ / TY, B_);   // (4, 16, 4) = 256 blocks
    dim3 block(THREADS);               // 448 (432 active)
    corr_kernel<<<grid, block>>>(tm1, tm2, out);
}

// round 14
// speedup vs baseline: 1.3262x; 1.0251x over previous
#include <cuda.h>
#include <cuda_runtime.h>
#include <cstdint>
#include <dlfcn.h>

#define B_  4
#define C_  256
#define H_  96
#define W_  128
#define P_  9
#define HW_ (H_ * W_)
#define CHW_ (C_ * H_ * W_)

#define TX  32           // x pixels per block
#define TY  6            // y pixels per block
#define PT  4            // x pixels per thread
#define ACTIVE 432       // 8g * 9dy * 6yy
#define THREADS 448      // padded to warp multiple (14 warps)
#define CC  16           // channels per stage
#define NSTAGE (C_ / CC) // 16
#define NBUF 2           // double buffer, prefetch distance 1
#define HALO_W  40       // halo row width (floats); 160B rows
#define HALO_H  14       // TY + 8

#define S2F_PER (CC * HALO_H * HALO_W)   // 8960 floats / buffer
#define S1F_PER (CC * TY * TX)           // 3072 floats / buffer
#define S2B_PER (S2F_PER * 4)            // 35840 B
#define S1B_PER (S1F_PER * 4)            // 12288 B
#define TX_BYTES ((uint32_t)(S1B_PER + S2B_PER))  // 48128 per stage (OOB fill counts)

typedef unsigned long long u64;

// ---- mbarrier primitives (proven forms) ----
__device__ __forceinline__ void mbar_init(uint32_t mbar, uint32_t cnt) {
    asm volatile("mbarrier.init.shared.b64 [%0], %1;" :: "r"(mbar), "r"(cnt) : "memory");
}
__device__ __forceinline__ void mbar_expect_tx(uint32_t mbar, uint32_t tx) {
    asm volatile("mbarrier.arrive.expect_tx.shared.b64 _, [%0], %1;"
                 :: "r"(mbar), "r"(tx) : "memory");
}
__device__ __forceinline__ void mbar_wait(uint32_t mbar, uint32_t parity) {
    uint32_t done;
    asm volatile(
        "{\n\t"
        ".reg .pred p;\n\t"
        "mbarrier.try_wait.parity.acquire.cta.shared::cta.b64 p, [%1], %2;\n\t"
        "selp.b32 %0, 1, 0, p;\n\t"
        "}"
        : "=r"(done) : "r"(mbar), "r"(parity) : "memory");
    if (!done) {
        asm volatile(
            "{\n\t"
            ".reg .pred P1;\n\t"
            "WAIT_LOOP_%=:\n\t"
            "mbarrier.try_wait.parity.acquire.cta.shared::cta.b64 P1, [%0], %1, 0x989680;\n\t"
            "@P1 bra.uni WAIT_DONE_%=;\n\t"
            "bra.uni WAIT_LOOP_%=;\n\t"
            "WAIT_DONE_%=:\n\t"
            "}"
            :: "r"(mbar), "r"(parity) : "memory");
    }
}
__device__ __forceinline__ void tma4d(uint32_t dst, const CUtensorMap* m,
                                      int x, int y, int z, int w, uint32_t mbar) {
    asm volatile(
        "cp.async.bulk.tensor.4d.shared::cta.global.tile.mbarrier::complete_tx::bytes "
        "[%0], [%1, {%2, %3, %4, %5}], [%6];"
        :: "r"(dst), "l"(m), "r"(x), "r"(y), "r"(z), "r"(w), "r"(mbar) : "memory");
}
__device__ __forceinline__ void fence_async_shared() {
    asm volatile("fence.proxy.async.shared::cta;" ::: "memory");
}

// ---- packed fp32 math ----
__device__ __forceinline__ u64 pk2(float lo, float hi) {
    u64 r;
    asm("mov.b64 %0, {%1, %2};" : "=l"(r) : "f"(lo), "f"(hi));
    return r;
}
__device__ __forceinline__ void fma2(u64& d, u64 a, u64 b) {
    asm("fma.rn.f32x2 %0, %1, %2, %0;" : "+l"(d) : "l"(a), "l"(b));
}
__device__ __forceinline__ void unpk2(float& lo, float& hi, u64 v) {
    asm("mov.b64 {%0, %1}, %2;" : "=f"(lo), "=f"(hi) : "l"(v));
}
// aligned 8B shared load (two consecutive floats as packed u64)
__device__ __forceinline__ u64 lds64(const float* p) {
    u64 r;
    asm("ld.shared.b64 %0, [%1];" : "=l"(r)
        : "l"((const float*)__builtin_assume_aligned(p, 8)));
    return r;
}

__global__ void __launch_bounds__(THREADS, 2)
corr_kernel(const __grid_constant__ CUtensorMap tm1,
            const __grid_constant__ CUtensorMap tm2,
            float* __restrict__ out)
{
    __shared__ __align__(128) float s2[NBUF][S2F_PER];  // in2 halo tiles
    __shared__ __align__(128) float s1[NBUF][S1F_PER];  // in1 tiles
    __shared__ __align__(8)   u64   fullb[NBUF];

    const int tid = threadIdx.x;
    const int b   = blockIdx.z;
    const int y0  = blockIdx.y * TY;
    const int x0  = blockIdx.x * TX;

    const uint32_t s2base = (uint32_t)__cvta_generic_to_shared(&s2[0][0]);
    const uint32_t s1base = (uint32_t)__cvta_generic_to_shared(&s1[0][0]);
    const uint32_t fbase  = (uint32_t)__cvta_generic_to_shared(&fullb[0]);

    // ---- compute roles: tid = (yy*9 + dy)*8 + g ; pads clamp yy (stores guarded) ----
    const bool active = (tid < ACTIVE);
    const int g   = tid & 7;
    const int dy  = (tid >> 3) % 9;
    const int yyr = tid / 72;
    const int yy  = active ? yyr : (TY - 1);

    u64 acc2[PT / 2][P_];
    #pragma unroll
    for (int t = 0; t < PT / 2; t++)
        #pragma unroll
        for (int d = 0; d < P_; d++)
            acc2[t][d] = 0ull;

    const int w_off = (yy + dy) * HALO_W + 4 * g;   // within s2 buffer (floats)
    const int a_off = yy * TX + 4 * g;              // within s1 buffer (floats)

    // ---- init mbarriers ----
    if (tid == 0) {
        #pragma unroll
        for (int i = 0; i < NBUF; i++)
            mbar_init(fbase + 8u * i, 1);
        fence_async_shared();
    }
    __syncthreads();

    // ---- prologue: fill stage 0 -> buf0, stage 1 -> buf1 (tid 0 only) ----
    if (tid == 0) {
        #pragma unroll
        for (int ps = 0; ps < 2; ps++) {
            uint32_t mb = fbase + 8u * ps;
            mbar_expect_tx(mb, TX_BYTES);
            tma4d(s1base + ps * S1B_PER, &tm1, x0,     y0,     ps * CC, b, mb);
            tma4d(s2base + ps * S2B_PER, &tm2, x0 - 4, y0 - 4, ps * CC, b, mb);
        }
    }

    #pragma unroll 1
    for (int st = 0; st < NSTAGE; st++) {
        if (st >= 1) {
            __syncthreads();   // stage st-1 fully drained by all warps
            if (tid == 0 && st + 1 < NSTAGE) {
                const int pb = (st + 1) % NBUF;    // == (st-1) % NBUF
                uint32_t mb = fbase + 8u * pb;
                mbar_expect_tx(mb, TX_BYTES);
                tma4d(s1base + pb * S1B_PER, &tm1, x0,     y0,     (st + 1) * CC, b, mb);
                tma4d(s2base + pb * S2B_PER, &tm2, x0 - 4, y0 - 4, (st + 1) * CC, b, mb);
            }
        }

        // wait for stage st data (issued one stage ahead)
        mbar_wait(fbase + 8u * (st % NBUF), (uint32_t)((st / NBUF) & 1));

        const float* wp = &s2[st % NBUF][w_off];
        const float* ap = &s1[st % NBUF][a_off];

        #pragma unroll 4
        for (int cc = 0; cc < CC; cc++) {
            const float4* wp4 = reinterpret_cast<const float4*>(wp);
            float4 w0 = wp4[0], w1 = wp4[1], w2 = wp4[2];
            u64 av0 = lds64(ap);        // (a[0], a[1]) packed
            u64 av1 = lds64(ap + 2);    // (a[2], a[3]) packed

            float wf[12];
            wf[0] = w0.x; wf[1]  = w0.y; wf[2]  = w0.z; wf[3]  = w0.w;
            wf[4] = w1.x; wf[5]  = w1.y; wf[6]  = w1.z; wf[7]  = w1.w;
            wf[8] = w2.x; wf[9]  = w2.y; wf[10] = w2.z; wf[11] = w2.w;

            // streaming window pairs: live wq = 1 register pair
            #pragma unroll
            for (int k = 0; k < 11; k++) {
                u64 wq = pk2(wf[k], wf[k + 1]);
                if (k <= 8) fma2(acc2[0][k], av0, wq);
                if (k >= 2) fma2(acc2[1][k - 2], av1, wq);
            }

            wp += HALO_H * HALO_W;
            ap += TY * TX;
        }
    }

    // ---- write output: out[b][dy][d][y0+yy][x0+4g .. +3] ----
    if (active) {
        const size_t hw = (size_t)HW_;
        float* obase = out + (((size_t)b * P_ + dy) * P_) * hw
                     + (size_t)(y0 + yy) * W_ + x0 + 4 * g;
        #pragma unroll
        for (int d = 0; d < P_; d++) {
            float4 v;
            unpk2(v.x, v.y, acc2[0][d]);
            unpk2(v.z, v.w, acc2[1][d]);
            *reinterpret_cast<float4*>(obase + (size_t)d * hw) = v;
        }
    }
}

// ---- host: resolve cuTensorMapEncodeTiled robustly (no -lcuda needed) ----
typedef CUresult (*EncodeTiledFn)(
    CUtensorMap*, CUtensorMapDataType, cuuint32_t, void*,
    const cuuint64_t*, const cuuint64_t*, const cuuint32_t*, const cuuint32_t*,
    CUtensorMapInterleave, CUtensorMapSwizzle, CUtensorMapL2promotion,
    CUtensorMapFloatOOBfill);

static EncodeTiledFn resolve_encode_fn() {
    void* fn = nullptr;
#if CUDART_VERSION >= 12050
    cudaDriverEntryPointQueryResult qres = cudaDriverEntryPointSuccess;
    if (cudaGetDriverEntryPointByVersion("cuTensorMapEncodeTiled", &fn, 12000,
                                         cudaEnableDefault, &qres) == cudaSuccess
        && qres == cudaDriverEntryPointSuccess && fn)
        return (EncodeTiledFn)fn;
    fn = nullptr;
#endif
    void* h = dlopen("libcuda.so.1", RTLD_LAZY | RTLD_GLOBAL);
    if (!h) h = dlopen("libcuda.so", RTLD_LAZY | RTLD_GLOBAL);
    if (h) fn = dlsym(h, "cuTensorMapEncodeTiled");
    if (!fn) fn = dlsym(RTLD_DEFAULT, "cuTensorMapEncodeTiled");
    return (EncodeTiledFn)fn;
}

extern "C" void kernel_launch(void* const* d_in, const int* in_sizes, int n_in,
                              void* d_out, int out_size) {
    void* in1 = d_in[0];
    void* in2 = d_in[1];
    float* out = (float*)d_out;

    EncodeTiledFn enc = resolve_encode_fn();
    if (!enc) return;

    cuuint64_t dims[4]    = {W_, H_, C_, B_};
    cuuint64_t strides[3] = {(cuuint64_t)W_ * 4,
                             (cuuint64_t)HW_ * 4,
                             (cuuint64_t)CHW_ * 4};
    cuuint32_t estr[4]    = {1, 1, 1, 1};

    CUtensorMap tm1, tm2;
    cuuint32_t box1[4] = {TX, TY, CC, 1};            // in1 tile (128B rows)
    enc(&tm1, CU_TENSOR_MAP_DATA_TYPE_FLOAT32, 4, in1, dims, strides, box1, estr,
        CU_TENSOR_MAP_INTERLEAVE_NONE, CU_TENSOR_MAP_SWIZZLE_NONE,
        CU_TENSOR_MAP_L2_PROMOTION_L2_128B, CU_TENSOR_MAP_FLOAT_OOB_FILL_NONE);

    cuuint32_t box2[4] = {HALO_W, HALO_H, CC, 1};    // in2 halo (OOB zero-filled)
    enc(&tm2, CU_TENSOR_MAP_DATA_TYPE_FLOAT32, 4, in2, dims, strides, box2, estr,
        CU_TENSOR_MAP_INTERLEAVE_NONE, CU_TENSOR_MAP_SWIZZLE_NONE,
        CU_TENSOR_MAP_L2_PROMOTION_L2_128B, CU_TENSOR_MAP_FLOAT_OOB_FILL_NONE);

    dim3 grid(W_ / TX, H_ / TY, B_);   // (4, 16, 4) = 256 blocks
    dim3 block(THREADS);               // 448 (432 active)
    corr_kernel<<<grid, block>>>(tm1, tm2, out);
}

// round 15
// speedup vs baseline: 1.3564x; 1.0228x over previous
#include <cuda.h>
#include <cuda_runtime.h>
#include <cstdint>
#include <dlfcn.h>

#define B_  4
#define C_  256
#define H_  96
#define W_  128
#define P_  9
#define HW_ (H_ * W_)
#define CHW_ (C_ * H_ * W_)

#define TX  32           // x pixels per block
#define TY  6            // y pixels per block
#define PT  8            // x pixels per thread
#define ACTIVE 216       // 4g * 9dy * 6yy
#define THREADS 224      // padded to warp multiple (7 warps)
#define CC  8            // channels per stage
#define NSTAGE (C_ / CC) // 32
#define NBUF 3           // triple buffer, prefetch distance 2
#define HALO_W  44       // halo row width INCLUDING pad (TMA box width); 176B rows -> odd phase shift, conflict-free
#define HALO_H  14       // TY + 8

#define S2F_PER (CC * HALO_H * HALO_W)   // 4928 floats / buffer
#define S1F_PER (CC * TY * TX)           // 1536 floats / buffer
#define S2B_PER (S2F_PER * 4)            // 19712 B
#define S1B_PER (S1F_PER * 4)            // 6144 B
#define TX_BYTES ((uint32_t)(S1B_PER + S2B_PER))  // 25856 per stage (OOB fill counts)

typedef unsigned long long u64;

// ---- mbarrier primitives (proven forms) ----
__device__ __forceinline__ void mbar_init(uint32_t mbar, uint32_t cnt) {
    asm volatile("mbarrier.init.shared.b64 [%0], %1;" :: "r"(mbar), "r"(cnt) : "memory");
}
__device__ __forceinline__ void mbar_expect_tx(uint32_t mbar, uint32_t tx) {
    asm volatile("mbarrier.arrive.expect_tx.shared.b64 _, [%0], %1;"
                 :: "r"(mbar), "r"(tx) : "memory");
}
__device__ __forceinline__ void mbar_wait(uint32_t mbar, uint32_t parity) {
    uint32_t done;
    asm volatile(
        "{\n\t"
        ".reg .pred p;\n\t"
        "mbarrier.try_wait.parity.acquire.cta.shared::cta.b64 p, [%1], %2;\n\t"
        "selp.b32 %0, 1, 0, p;\n\t"
        "}"
        : "=r"(done) : "r"(mbar), "r"(parity) : "memory");
    if (!done) {
        asm volatile(
            "{\n\t"
            ".reg .pred P1;\n\t"
            "WAIT_LOOP_%=:\n\t"
            "mbarrier.try_wait.parity.acquire.cta.shared::cta.b64 P1, [%0], %1, 0x989680;\n\t"
            "@P1 bra.uni WAIT_DONE_%=;\n\t"
            "bra.uni WAIT_LOOP_%=;\n\t"
            "WAIT_DONE_%=:\n\t"
            "}"
            :: "r"(mbar), "r"(parity) : "memory");
    }
}
__device__ __forceinline__ void tma4d(uint32_t dst, const CUtensorMap* m,
                                      int x, int y, int z, int w, uint32_t mbar) {
    asm volatile(
        "cp.async.bulk.tensor.4d.shared::cta.global.tile.mbarrier::complete_tx::bytes "
        "[%0], [%1, {%2, %3, %4, %5}], [%6];"
        :: "r"(dst), "l"(m), "r"(x), "r"(y), "r"(z), "r"(w), "r"(mbar) : "memory");
}
__device__ __forceinline__ void fence_async_shared() {
    asm volatile("fence.proxy.async.shared::cta;" ::: "memory");
}

// ---- packed fp32 math ----
__device__ __forceinline__ u64 pk2(float lo, float hi) {
    u64 r;
    asm("mov.b64 %0, {%1, %2};" : "=l"(r) : "f"(lo), "f"(hi));
    return r;
}
__device__ __forceinline__ void fma2(u64& d, u64 a, u64 b) {
    asm("fma.rn.f32x2 %0, %1, %2, %0;" : "+l"(d) : "l"(a), "l"(b));
}
__device__ __forceinline__ void unpk2(float& lo, float& hi, u64 v) {
    asm("mov.b64 {%0, %1}, %2;" : "=f"(lo), "=f"(hi) : "l"(v));
}

__global__ void __launch_bounds__(THREADS, 2)
corr_kernel(const __grid_constant__ CUtensorMap tm1,
            const __grid_constant__ CUtensorMap tm2,
            float* __restrict__ out)
{
    __shared__ __align__(128) float s2[NBUF][S2F_PER];  // in2 halo tiles (176B rows)
    __shared__ __align__(128) float s1[NBUF][S1F_PER];  // in1 tiles
    __shared__ __align__(8)   u64   fullb[NBUF];

    const int tid = threadIdx.x;
    const int b   = blockIdx.z;
    const int y0  = blockIdx.y * TY;
    const int x0  = blockIdx.x * TX;

    const uint32_t s2base = (uint32_t)__cvta_generic_to_shared(&s2[0][0]);
    const uint32_t s1base = (uint32_t)__cvta_generic_to_shared(&s1[0][0]);
    const uint32_t fbase  = (uint32_t)__cvta_generic_to_shared(&fullb[0]);

    // ---- compute roles: tid = (yy*9 + dy)*4 + g ; pads clamp yy (stores guarded) ----
    const bool active = (tid < ACTIVE);
    const int g   = tid & 3;          // x-group (0..3), 8 px each
    const int dy  = (tid >> 2) % 9;   // shift row
    const int yyr = tid / 36;
    const int yy  = active ? yyr : (TY - 1);

    // acc2[t][d]: outputs x = 8g+2t, 8g+2t+1 at shift dx=d
    u64 acc2[PT / 2][P_];
    #pragma unroll
    for (int t = 0; t < PT / 2; t++)
        #pragma unroll
        for (int d = 0; d < P_; d++)
            acc2[t][d] = 0ull;

    const int w_off = (yy + dy) * HALO_W + 8 * g;   // within s2 buffer (floats)
    const int a_off = yy * TX + 8 * g;              // within s1 buffer (floats)

    // ---- init mbarriers ----
    if (tid == 0) {
        #pragma unroll
        for (int i = 0; i < NBUF; i++)
            mbar_init(fbase + 8u * i, 1);
        fence_async_shared();
    }
    __syncthreads();

    // ---- prologue: issue stages 0 and 1 (tid 0 only) ----
    if (tid == 0) {
        #pragma unroll
        for (int ps = 0; ps < 2; ps++) {
            uint32_t mb = fbase + 8u * ps;
            mbar_expect_tx(mb, TX_BYTES);
            tma4d(s1base + ps * S1B_PER, &tm1, x0,     y0,     ps * CC, b, mb);
            tma4d(s2base + ps * S2B_PER, &tm2, x0 - 4, y0 - 4, ps * CC, b, mb);
        }
    }

    #pragma unroll 1
    for (int st = 0; st < NSTAGE; st++) {
        __syncthreads();   // all reads of buffer (st+2)%3 (done at stage st-1)
                           // complete before it is refilled below
        if (tid == 0 && st + 2 < NSTAGE) {
            const int pb = (st + 2) % NBUF;
            uint32_t mb = fbase + 8u * pb;
            mbar_expect_tx(mb, TX_BYTES);
            tma4d(s1base + pb * S1B_PER, &tm1, x0,     y0,     (st + 2) * CC, b, mb);
            tma4d(s2base + pb * S2B_PER, &tm2, x0 - 4, y0 - 4, (st + 2) * CC, b, mb);
        }

        // wait for stage st data
        mbar_wait(fbase + 8u * (st % NBUF), (uint32_t)((st / NBUF) & 1));

        const float* wp = &s2[st % NBUF][w_off];
        const float* ap = &s1[st % NBUF][a_off];

        #pragma unroll 2
        for (int cc = 0; cc < CC; cc++) {
            const float4* wp4 = reinterpret_cast<const float4*>(wp);
            float4 w0 = wp4[0], w1 = wp4[1], w2 = wp4[2], w3 = wp4[3];
            const float4* ap4 = reinterpret_cast<const float4*>(ap);
            float4 a0 = ap4[0], a1 = ap4[1];

            u64 av0 = pk2(a0.x, a0.y);
            u64 av1 = pk2(a0.z, a0.w);
            u64 av2 = pk2(a1.x, a1.y);
            u64 av3 = pk2(a1.z, a1.w);

            float wf[16];
            wf[0]  = w0.x; wf[1]  = w0.y; wf[2]  = w0.z; wf[3]  = w0.w;
            wf[4]  = w1.x; wf[5]  = w1.y; wf[6]  = w1.z; wf[7]  = w1.w;
            wf[8]  = w2.x; wf[9]  = w2.y; wf[10] = w2.z; wf[11] = w2.w;
            wf[12] = w3.x; wf[13] = w3.y; wf[14] = w3.z; wf[15] = w3.w;

            // streaming window pairs: live wq = 1 register pair
            #pragma unroll
            for (int k = 0; k < 15; k++) {
                u64 wq = pk2(wf[k], wf[k + 1]);
                if (k <= 8)           fma2(acc2[0][k],     av0, wq);
                if (k >= 2 && k <= 10) fma2(acc2[1][k - 2], av1, wq);
                if (k >= 4 && k <= 12) fma2(acc2[2][k - 4], av2, wq);
                if (k >= 6)           fma2(acc2[3][k - 6], av3, wq);
            }

            wp += HALO_H * HALO_W;
            ap += TY * TX;
        }
    }

    // ---- write output: out[b][dy][d][y0+yy][x0+8g .. +7] ----
    if (active) {
        const size_t hw = (size_t)HW_;
        float* obase = out + (((size_t)b * P_ + dy) * P_) * hw
                     + (size_t)(y0 + yy) * W_ + x0 + 8 * g;
        #pragma unroll
        for (int d = 0; d < P_; d++) {
            float4 v0, v1;
            unpk2(v0.x, v0.y, acc2[0][d]);
            unpk2(v0.z, v0.w, acc2[1][d]);
            unpk2(v1.x, v1.y, acc2[2][d]);
            unpk2(v1.z, v1.w, acc2[3][d]);
            *reinterpret_cast<float4*>(obase + (size_t)d * hw)     = v0;
            *reinterpret_cast<float4*>(obase + (size_t)d * hw + 4) = v1;
        }
    }
}

// ---- host: resolve cuTensorMapEncodeTiled robustly (no -lcuda needed) ----
typedef CUresult (*EncodeTiledFn)(
    CUtensorMap*, CUtensorMapDataType, cuuint32_t, void*,
    const cuuint64_t*, const cuuint64_t*, const cuuint32_t*, const cuuint32_t*,
    CUtensorMapInterleave, CUtensorMapSwizzle, CUtensorMapL2promotion,
    CUtensorMapFloatOOBfill);

static EncodeTiledFn resolve_encode_fn() {
    void* fn = nullptr;
#if CUDART_VERSION >= 12050
    cudaDriverEntryPointQueryResult qres = cudaDriverEntryPointSuccess;
    if (cudaGetDriverEntryPointByVersion("cuTensorMapEncodeTiled", &fn, 12000,
                                         cudaEnableDefault, &qres) == cudaSuccess
        && qres == cudaDriverEntryPointSuccess && fn)
        return (EncodeTiledFn)fn;
    fn = nullptr;
#endif
    void* h = dlopen("libcuda.so.1", RTLD_LAZY | RTLD_GLOBAL);
    if (!h) h = dlopen("libcuda.so", RTLD_LAZY | RTLD_GLOBAL);
    if (h) fn = dlsym(h, "cuTensorMapEncodeTiled");
    if (!fn) fn = dlsym(RTLD_DEFAULT, "cuTensorMapEncodeTiled");
    return (EncodeTiledFn)fn;
}

extern "C" void kernel_launch(void* const* d_in, const int* in_sizes, int n_in,
                              void* d_out, int out_size) {
    void* in1 = d_in[0];
    void* in2 = d_in[1];
    float* out = (float*)d_out;

    EncodeTiledFn enc = resolve_encode_fn();
    if (!enc) return;

    cuuint64_t dims[4]    = {W_, H_, C_, B_};
    cuuint64_t strides[3] = {(cuuint64_t)W_ * 4,
                             (cuuint64_t)HW_ * 4,
                             (cuuint64_t)CHW_ * 4};
    cuuint32_t estr[4]    = {1, 1, 1, 1};

    CUtensorMap tm1, tm2;
    cuuint32_t box1[4] = {TX, TY, CC, 1};            // in1 tile (128B rows)
    enc(&tm1, CU_TENSOR_MAP_DATA_TYPE_FLOAT32, 4, in1, dims, strides, box1, estr,
        CU_TENSOR_MAP_INTERLEAVE_NONE, CU_TENSOR_MAP_SWIZZLE_NONE,
        CU_TENSOR_MAP_L2_PROMOTION_L2_128B, CU_TENSOR_MAP_FLOAT_OOB_FILL_NONE);

    // halo box is 44 wide: 40 needed + 4 pad (zero-filled OOB at right edge).
    // 176B smem rows give an odd 16B-phase shift -> conflict-free PT=8 loads.
    cuuint32_t box2[4] = {HALO_W, HALO_H, CC, 1};
    enc(&tm2, CU_TENSOR_MAP_DATA_TYPE_FLOAT32, 4, in2, dims, strides, box2, estr,
        CU_TENSOR_MAP_INTERLEAVE_NONE, CU_TENSOR_MAP_SWIZZLE_NONE,
        CU_TENSOR_MAP_L2_PROMOTION_L2_128B, CU_TENSOR_MAP_FLOAT_OOB_FILL_NONE);

    dim3 grid(W_ / TX, H_ / TY, B_);   // (4, 16, 4) = 256 blocks
    dim3 block(THREADS);               // 224 (216 active)
    corr_kernel<<<grid, block>>>(tm1, tm2, out);
}